// round 4
// baseline (speedup 1.0000x reference)
#include <cuda_runtime.h>
#include <cstdint>

#define NN 60000
#define EE 600000
#define DD 128
#define SLOPE 0.01f
#define SBLK 512
#define SCANB 59

typedef unsigned long long ull;

// ---------------- device scratch (static, no allocation) ----------------
__device__ int   g_is64;
__device__ int   g_cnt[NN];
__device__ int   g_incl[NN];
__device__ int   g_part[64];
__device__ int   g_rowstart[NN + 1];
__device__ int   g_next[NN];
__device__ int2  g_edge[EE];          // (src, __float_as_int(dinv[src]))
__device__ float g_dinv[NN];
__device__ float g_xw[(size_t)NN * DD];
__device__ float g_h[(size_t)NN * DD];
__device__ double g_bsum[SBLK * DD];
__device__ double g_bsq[SBLK * DD];
__device__ float g_scale[DD];
__device__ float g_shift[DD];

// packed f32x2 FMA: d = a*b + d  (sm_103a FFMA2)
#define FMA2(d, a, b) asm("fma.rn.f32x2 %0, %1, %2, %0;" : "+l"(d) : "l"(a), "l"(b))

// ---------------- init: edge dtype detect + zero counters ----------------
__global__ void k_init(const void* ei) {
    int i = blockIdx.x * blockDim.x + threadIdx.x;
    if (i < NN) g_cnt[i] = 0;
    if (i == 0) {
        const long long* q = (const long long*)ei;
        int ok = 1;
        for (int j = 0; j < 256; j++) {
            long long v = q[j];
            if (v < 0 || v >= NN) { ok = 0; break; }
        }
        g_is64 = ok;
    }
}

__device__ __forceinline__ int edge_at(const void* p, int idx, int is64) {
    // little-endian: low 32 bits of int64 suffice (values < 2^31)
    return is64 ? ((const int*)p)[2 * idx] : ((const int*)p)[idx];
}

__global__ void k_hist(const void* ei) {
    int e = blockIdx.x * blockDim.x + threadIdx.x;
    if (e < EE) {
        int d = edge_at(ei, EE + e, g_is64);
        atomicAdd(&g_cnt[d], 1);
    }
}

// scan over degree counts (block-inclusive) + dinv
__global__ void k_scan1() {
    __shared__ int s[1024];
    int i = blockIdx.x * 1024 + threadIdx.x;
    int x = (i < NN) ? g_cnt[i] : 0;
    s[threadIdx.x] = x;
    __syncthreads();
    for (int off = 1; off < 1024; off <<= 1) {
        int v = (threadIdx.x >= off) ? s[threadIdx.x - off] : 0;
        __syncthreads();
        s[threadIdx.x] += v;
        __syncthreads();
    }
    if (i < NN) {
        g_incl[i] = s[threadIdx.x];
        g_dinv[i] = rsqrtf((float)(x + 1));  // +1 self loop
    }
    if (threadIdx.x == 1023) g_part[blockIdx.x] = s[1023];
}

// combined cross-block prefix + rowstart
__global__ void k_scan3() {
    __shared__ int sp[64];
    if (threadIdx.x < 64) sp[threadIdx.x] = (threadIdx.x < SCANB) ? g_part[threadIdx.x] : 0;
    __syncthreads();
    int i = blockIdx.x * blockDim.x + threadIdx.x;
    if (i < NN) {
        int blk = i >> 10;
        int pre = 0;
        for (int b = 0; b < blk; b++) pre += sp[b];
        int rs = g_incl[i] - g_cnt[i] + pre;
        g_rowstart[i] = rs;
        g_next[i] = rs;
    }
    if (i == 0) g_rowstart[NN] = EE;
}

__global__ void k_fill(const void* ei) {
    int e = blockIdx.x * blockDim.x + threadIdx.x;
    if (e < EE) {
        int is64 = g_is64;
        int s = edge_at(ei, e, is64);
        int d = edge_at(ei, EE + e, is64);
        int pos = atomicAdd(&g_next[d], 1);
        g_edge[pos] = make_int2(s, __float_as_int(g_dinv[s]));
    }
}

// ---------------- GEMM: C[M,128] = f(A)[M,128] @ W[128,128], FFMA2 ----------
__global__ __launch_bounds__(256, 2) void k_gemm(
    const float* __restrict__ A, const float* __restrict__ W,
    float* __restrict__ C,
    const float* __restrict__ scale, const float* __restrict__ shift, int act)
{
    __shared__ float As2[8][256];  // duplicated pairs for FMA2 operand feed
    __shared__ float Ws[8][128];

    int t = threadIdx.x;
    int r0 = blockIdx.x * 128;
    int ty = t >> 4, tx = t & 15;
    int arow = t >> 1, ahalf = t & 1;
    int wrow = t >> 5, wcol = (t & 31) * 4;

    ull acc2[8][4];
#pragma unroll
    for (int i = 0; i < 8; i++)
#pragma unroll
        for (int j = 0; j < 4; j++) acc2[i][j] = 0ull;

    float4 av = make_float4(0.f, 0.f, 0.f, 0.f);
    int gr = r0 + arow;
    if (gr < NN)
        av = *reinterpret_cast<const float4*>(A + (size_t)gr * DD + ahalf * 4);
    float4 wv = *reinterpret_cast<const float4*>(W + (size_t)wrow * DD + wcol);

    for (int k0 = 0; k0 < 128; k0 += 8) {
        float4 ta = av;
        int c0 = k0 + ahalf * 4;
        if (scale) {
            ta.x = ta.x * scale[c0 + 0] + shift[c0 + 0];
            ta.y = ta.y * scale[c0 + 1] + shift[c0 + 1];
            ta.z = ta.z * scale[c0 + 2] + shift[c0 + 2];
            ta.w = ta.w * scale[c0 + 3] + shift[c0 + 3];
            if (act) {
                ta.x = ta.x >= 0.f ? ta.x : SLOPE * ta.x;
                ta.y = ta.y >= 0.f ? ta.y : SLOPE * ta.y;
                ta.z = ta.z >= 0.f ? ta.z : SLOPE * ta.z;
                ta.w = ta.w >= 0.f ? ta.w : SLOPE * ta.w;
            }
        }
        *reinterpret_cast<float2*>(&As2[ahalf * 4 + 0][2 * arow]) = make_float2(ta.x, ta.x);
        *reinterpret_cast<float2*>(&As2[ahalf * 4 + 1][2 * arow]) = make_float2(ta.y, ta.y);
        *reinterpret_cast<float2*>(&As2[ahalf * 4 + 2][2 * arow]) = make_float2(ta.z, ta.z);
        *reinterpret_cast<float2*>(&As2[ahalf * 4 + 3][2 * arow]) = make_float2(ta.w, ta.w);
        *reinterpret_cast<float4*>(&Ws[wrow][wcol]) = wv;
        __syncthreads();

        if (k0 + 8 < 128) {
            if (gr < NN)
                av = *reinterpret_cast<const float4*>(A + (size_t)gr * DD + (k0 + 8) + ahalf * 4);
            wv = *reinterpret_cast<const float4*>(W + (size_t)(k0 + 8 + wrow) * DD + wcol);
        }

#pragma unroll
        for (int kk = 0; kk < 8; kk++) {
            ulonglong2 pa0 = *reinterpret_cast<const ulonglong2*>(&As2[kk][ty * 16 + 0]);
            ulonglong2 pa1 = *reinterpret_cast<const ulonglong2*>(&As2[kk][ty * 16 + 4]);
            ulonglong2 pa2 = *reinterpret_cast<const ulonglong2*>(&As2[kk][ty * 16 + 8]);
            ulonglong2 pa3 = *reinterpret_cast<const ulonglong2*>(&As2[kk][ty * 16 + 12]);
            ulonglong2 pb0 = *reinterpret_cast<const ulonglong2*>(&Ws[kk][tx * 8 + 0]);
            ulonglong2 pb1 = *reinterpret_cast<const ulonglong2*>(&Ws[kk][tx * 8 + 4]);
            ull a2[8] = {pa0.x, pa0.y, pa1.x, pa1.y, pa2.x, pa2.y, pa3.x, pa3.y};
            ull b2[4] = {pb0.x, pb0.y, pb1.x, pb1.y};
#pragma unroll
            for (int i = 0; i < 8; i++) {
                FMA2(acc2[i][0], a2[i], b2[0]);
                FMA2(acc2[i][1], a2[i], b2[1]);
                FMA2(acc2[i][2], a2[i], b2[2]);
                FMA2(acc2[i][3], a2[i], b2[3]);
            }
        }
        __syncthreads();
    }

#pragma unroll
    for (int i = 0; i < 8; i++) {
        int orow = r0 + ty * 8 + i;
        if (orow < NN) {
            *reinterpret_cast<ulonglong2*>(C + (size_t)orow * DD + tx * 8 + 0) =
                make_ulonglong2(acc2[i][0], acc2[i][1]);
            *reinterpret_cast<ulonglong2*>(C + (size_t)orow * DD + tx * 8 + 4) =
                make_ulonglong2(acc2[i][2], acc2[i][3]);
        }
    }
}

// ---- aggregation: warp/node, software-pipelined + fully predicated --------
__global__ __launch_bounds__(256) void k_agg(
    const float* __restrict__ xw, float* __restrict__ outp)
{
    int w = (blockIdx.x * blockDim.x + threadIdx.x) >> 5;
    int lane = threadIdx.x & 31;
    if (w >= NN) return;
    float di = g_dinv[w];

    float4 acc = __ldg(reinterpret_cast<const float4*>(xw + (size_t)w * DD) + lane);
    float cself = di * di;
    acc.x *= cself; acc.y *= cself; acc.z *= cself; acc.w *= cself;

    int beg = g_rowstart[w], end = g_rowstart[w + 1];
    if (beg < end) {
        int last = end - 1;
        // prefetch first edge group (clamped)
        int2 E0 = __ldg(&g_edge[beg]);
        int2 E1 = __ldg(&g_edge[min(beg + 1, last)]);
        int2 E2 = __ldg(&g_edge[min(beg + 2, last)]);
        int2 E3 = __ldg(&g_edge[min(beg + 3, last)]);
        for (int i = beg; i < end; i += 4) {
            // prefetch next group while current rows load
            int2 N0, N1, N2, N3;
            int nb = i + 4;
            if (nb < end) {
                N0 = __ldg(&g_edge[nb]);
                N1 = __ldg(&g_edge[min(nb + 1, last)]);
                N2 = __ldg(&g_edge[min(nb + 2, last)]);
                N3 = __ldg(&g_edge[min(nb + 3, last)]);
            }
            float4 v0 = __ldg(reinterpret_cast<const float4*>(xw + (size_t)E0.x * DD) + lane);
            float4 v1 = __ldg(reinterpret_cast<const float4*>(xw + (size_t)E1.x * DD) + lane);
            float4 v2 = __ldg(reinterpret_cast<const float4*>(xw + (size_t)E2.x * DD) + lane);
            float4 v3 = __ldg(reinterpret_cast<const float4*>(xw + (size_t)E3.x * DD) + lane);
            float c0 = di * __int_as_float(E0.y);                       // slot 0 always valid
            float c1 = (i + 1 < end) ? di * __int_as_float(E1.y) : 0.f;
            float c2 = (i + 2 < end) ? di * __int_as_float(E2.y) : 0.f;
            float c3 = (i + 3 < end) ? di * __int_as_float(E3.y) : 0.f;
            acc.x = fmaf(c0, v0.x, acc.x); acc.y = fmaf(c0, v0.y, acc.y);
            acc.z = fmaf(c0, v0.z, acc.z); acc.w = fmaf(c0, v0.w, acc.w);
            acc.x = fmaf(c1, v1.x, acc.x); acc.y = fmaf(c1, v1.y, acc.y);
            acc.z = fmaf(c1, v1.z, acc.z); acc.w = fmaf(c1, v1.w, acc.w);
            acc.x = fmaf(c2, v2.x, acc.x); acc.y = fmaf(c2, v2.y, acc.y);
            acc.z = fmaf(c2, v2.z, acc.z); acc.w = fmaf(c2, v2.w, acc.w);
            acc.x = fmaf(c3, v3.x, acc.x); acc.y = fmaf(c3, v3.y, acc.y);
            acc.z = fmaf(c3, v3.z, acc.z); acc.w = fmaf(c3, v3.w, acc.w);
            E0 = N0; E1 = N1; E2 = N2; E3 = N3;
        }
    }
    reinterpret_cast<float4*>(outp + (size_t)w * DD)[lane] = acc;
}

// ---------------- BN stats (two-stage, fp64 partials) ----------------
__global__ __launch_bounds__(256) void k_stats1(const float* __restrict__ h) {
    __shared__ double s1[256], s2[256];
    int t = threadIdx.x;
    int d = t & 127, half = t >> 7;
    double sum = 0.0, sq = 0.0;
    for (int r = blockIdx.x * 2 + half; r < NN; r += gridDim.x * 2) {
        double v = (double)h[(size_t)r * DD + d];
        sum += v; sq += v * v;
    }
    s1[t] = sum; s2[t] = sq;
    __syncthreads();
    if (t < 128) {
        g_bsum[blockIdx.x * DD + t] = s1[t] + s1[t + 128];
        g_bsq [blockIdx.x * DD + t] = s2[t] + s2[t + 128];
    }
}

__global__ void k_stats2(const float* __restrict__ gw, const float* __restrict__ be, int nb) {
    int d = threadIdx.x;
    double sum = 0.0, sq = 0.0;
    for (int b = 0; b < nb; b++) { sum += g_bsum[b * DD + d]; sq += g_bsq[b * DD + d]; }
    double mu = sum / (double)NN;
    double var = sq / (double)NN - mu * mu;
    float inv = (float)(1.0 / sqrt(var + 1e-5));
    float scl = gw[d] * inv;
    g_scale[d] = scl;
    g_shift[d] = be[d] - (float)mu * scl;
}

__global__ void k_apply(float* __restrict__ h) {
    int idx = blockIdx.x * blockDim.x + threadIdx.x;
    if (idx < NN * DD) {
        int d = idx & 127;
        h[idx] = h[idx] * g_scale[d] + g_shift[d];
    }
}

// ---------------- host launcher ----------------
extern "C" void kernel_launch(void* const* d_in, const int* in_sizes, int n_in,
                              void* d_out, int out_size) {
    const float* x   = (const float*)d_in[0];
    const void*  ei  = d_in[1];
    const float* w0  = (const float*)d_in[2];
    const float* g0  = (const float*)d_in[4];
    const float* be0 = (const float*)d_in[5];
    const float* w1  = (const float*)d_in[6];
    const float* g1  = (const float*)d_in[8];
    const float* be1 = (const float*)d_in[9];
    const float* w2  = (const float*)d_in[10];
    const float* g2  = (const float*)d_in[12];
    const float* be2 = (const float*)d_in[13];
    float* out = (float*)d_out;

    float *xw, *h, *scl, *shf;
    cudaGetSymbolAddress((void**)&xw,  g_xw);
    cudaGetSymbolAddress((void**)&h,   g_h);
    cudaGetSymbolAddress((void**)&scl, g_scale);
    cudaGetSymbolAddress((void**)&shf, g_shift);

    const int TB = 256;
    int gbN = (NN + TB - 1) / TB;
    int gbE = (EE + TB - 1) / TB;
    int gbG = (NN + 127) / 128;
    int gbA = (NN * 32 + TB - 1) / TB;
    int gbP = (NN * DD + TB - 1) / TB;

    // build + layer-0 GEMM ordered so GEMM is the 4th launch (ncu -s window)
    k_init<<<gbN, TB>>>(ei);                              // 1
    k_hist<<<gbE, TB>>>(ei);                              // 2
    k_scan1<<<SCANB, 1024>>>();                           // 3 (+dinv)
    k_gemm<<<gbG, TB>>>(x, w0, xw, nullptr, nullptr, 0);  // 4 <- profiled
    k_scan3<<<gbN, TB>>>();                               // 5 (+cross-block prefix)
    k_fill<<<gbE, TB>>>(ei);                              // 6

    // layer 0 tail
    k_agg<<<gbA, TB>>>(xw, h);
    k_stats1<<<SBLK, TB>>>(h);
    k_stats2<<<1, DD>>>(g0, be0, SBLK);

    // layer 1 (BN0 + LeakyReLU fused into GEMM A-load)
    k_gemm<<<gbG, TB>>>(h, w1, xw, scl, shf, 1);
    k_agg<<<gbA, TB>>>(xw, h);
    k_stats1<<<SBLK, TB>>>(h);
    k_stats2<<<1, DD>>>(g1, be1, SBLK);

    // layer 2 (BN1 + LeakyReLU fused), final BN standalone
    k_gemm<<<gbG, TB>>>(h, w2, xw, scl, shf, 1);
    k_agg<<<gbA, TB>>>(xw, out);
    k_stats1<<<SBLK, TB>>>(out);
    k_stats2<<<1, DD>>>(g2, be2, SBLK);
    k_apply<<<gbP, TB>>>(out);
}

// round 5
// speedup vs baseline: 1.5745x; 1.5745x over previous
#include <cuda_runtime.h>
#include <cstdint>

#define NN 60000
#define EE 600000
#define DD 128
#define SLOPE 0.01f
#define BB 256            // build kernel blocks (must all be co-resident)
#define NBLK 7500         // agg stats partial blocks (60000/8)

typedef unsigned long long ull;

// ---------------- device scratch (static, no allocation) ----------------
__device__ int   g_is64;
__device__ int   g_cnt[NN];
__device__ int   g_part[BB];
__device__ int   g_rowstart[NN + 1];
__device__ int   g_next[NN];
__device__ int2  g_edge[EE];          // (src, __float_as_int(dinv[src]))
__device__ float g_dinv[NN];
__device__ float g_xw[(size_t)NN * DD];
__device__ float g_h[(size_t)NN * DD];
__device__ float g_psum[(size_t)NBLK * DD];
__device__ float g_psq[(size_t)NBLK * DD];
__device__ float g_scale[DD];
__device__ float g_shift[DD];
__device__ unsigned g_barcnt;   // zero-init; barrier resets it each use
__device__ unsigned g_epoch;    // monotonic across replays (deterministic work)

// packed f32x2 FMA: d = a*b + d  (sm_103a FFMA2)
#define FMA2(d, a, b) asm("fma.rn.f32x2 %0, %1, %2, %0;" : "+l"(d) : "l"(a), "l"(b))
// duplicate one fp32 into both lanes of a 64-bit pair (1 MOV, alu pipe)
#define PACK2(d, s) asm("mov.b64 %0, {%1, %1};" : "=l"(d) : "r"(s))

// ---------------- global spin barrier (BB blocks, all resident) ------------
__device__ __forceinline__ void gsync() {
    __syncthreads();
    if (threadIdx.x == 0) {
        __threadfence();
        unsigned e = atomicAdd(&g_epoch, 0u);
        if (atomicAdd(&g_barcnt, 1u) == BB - 1u) {
            g_barcnt = 0u;
            __threadfence();
            atomicAdd(&g_epoch, 1u);
        } else {
            while (((volatile unsigned*)&g_epoch)[0] == e) { __nanosleep(64); }
        }
        __threadfence();
    }
    __syncthreads();
}

__device__ __forceinline__ int edge_at(const void* p, int idx, int is64) {
    // little-endian: low 32 bits of int64 suffice (values < 2^31)
    return is64 ? ((const int*)p)[2 * idx] : ((const int*)p)[idx];
}

// ---------------- fused CSR build: zero+detect / hist / scan / fill --------
__global__ __launch_bounds__(256) void k_build(const void* ei) {
    int t = threadIdx.x, b = blockIdx.x;
    int gid = b * 256 + t;
    const int GSTR = BB * 256;

    // P0: dtype detect + zero counters
    if (gid == 0) {
        const long long* q = (const long long*)ei;
        int ok = 1;
        for (int j = 0; j < 256; j++) {
            long long v = q[j];
            if (v < 0 || v >= NN) { ok = 0; break; }
        }
        g_is64 = ok;
    }
    for (int i = gid; i < NN; i += GSTR) g_cnt[i] = 0;
    gsync();
    int is64 = g_is64;

    // P1: degree histogram
    for (int e = gid; e < EE; e += GSTR) {
        int d = edge_at(ei, EE + e, is64);
        atomicAdd(&g_cnt[d], 1);
    }
    gsync();

    // P2: dinv + intra-block inclusive scan (block b owns nodes [b*256, b*256+256))
    __shared__ int s[256];
    __shared__ int sp[256];
    int i = gid;
    int x = (i < NN) ? g_cnt[i] : 0;
    if (i < NN) g_dinv[i] = rsqrtf((float)(x + 1));   // +1 self loop
    s[t] = x;
    __syncthreads();
    for (int off = 1; off < 256; off <<= 1) {
        int v = (t >= off) ? s[t - off] : 0;
        __syncthreads();
        s[t] += v;
        __syncthreads();
    }
    int incl = s[t];
    if (t == 255) g_part[b] = incl;
    gsync();

    // P3: scan block partials, emit rowstart
    sp[t] = g_part[t];
    __syncthreads();
    for (int off = 1; off < 256; off <<= 1) {
        int v = (t >= off) ? sp[t - off] : 0;
        __syncthreads();
        sp[t] += v;
        __syncthreads();
    }
    int pre = (b > 0) ? sp[b - 1] : 0;
    if (i < NN) {
        int rs = pre + incl - x;
        g_rowstart[i] = rs;
        g_next[i] = rs;
    }
    if (gid == 0) g_rowstart[NN] = EE;
    gsync();

    // P4: fill edge array (src, dinv[src])
    for (int e = gid; e < EE; e += GSTR) {
        int sdx = edge_at(ei, e, is64);
        int dd  = edge_at(ei, EE + e, is64);
        int pos = atomicAdd(&g_next[dd], 1);
        g_edge[pos] = make_int2(sdx, __float_as_int(g_dinv[sdx]));
    }
}

// ---------------- GEMM: C[M,128] = f(A)[M,128] @ W[128,128], FFMA2 ----------
// A pairs built in registers (mov.b64 dup) -> 64B LDS per thread per kk.
__global__ __launch_bounds__(256, 2) void k_gemm(
    const float* __restrict__ A, const float* __restrict__ W,
    float* __restrict__ C,
    const float* __restrict__ scale, const float* __restrict__ shift, int act)
{
    __shared__ float As[8][128];
    __shared__ float Ws[8][128];

    int t = threadIdx.x;
    int r0 = blockIdx.x * 128;
    int ty = t >> 4, tx = t & 15;
    int arow = t >> 1, ahalf = t & 1;
    int wrow = t >> 5, wcol = (t & 31) * 4;

    ull acc2[8][4];
#pragma unroll
    for (int i = 0; i < 8; i++)
#pragma unroll
        for (int j = 0; j < 4; j++) acc2[i][j] = 0ull;

    float4 av = make_float4(0.f, 0.f, 0.f, 0.f);
    int gr = r0 + arow;
    if (gr < NN)
        av = *reinterpret_cast<const float4*>(A + (size_t)gr * DD + ahalf * 4);
    float4 wv = *reinterpret_cast<const float4*>(W + (size_t)wrow * DD + wcol);

    for (int k0 = 0; k0 < 128; k0 += 8) {
        float4 ta = av;
        int c0 = k0 + ahalf * 4;
        if (scale) {
            ta.x = ta.x * scale[c0 + 0] + shift[c0 + 0];
            ta.y = ta.y * scale[c0 + 1] + shift[c0 + 1];
            ta.z = ta.z * scale[c0 + 2] + shift[c0 + 2];
            ta.w = ta.w * scale[c0 + 3] + shift[c0 + 3];
            if (act) {
                ta.x = ta.x >= 0.f ? ta.x : SLOPE * ta.x;
                ta.y = ta.y >= 0.f ? ta.y : SLOPE * ta.y;
                ta.z = ta.z >= 0.f ? ta.z : SLOPE * ta.z;
                ta.w = ta.w >= 0.f ? ta.w : SLOPE * ta.w;
            }
        }
        As[ahalf * 4 + 0][arow] = ta.x;
        As[ahalf * 4 + 1][arow] = ta.y;
        As[ahalf * 4 + 2][arow] = ta.z;
        As[ahalf * 4 + 3][arow] = ta.w;
        *reinterpret_cast<float4*>(&Ws[wrow][wcol]) = wv;
        __syncthreads();

        if (k0 + 8 < 128) {
            if (gr < NN)
                av = *reinterpret_cast<const float4*>(A + (size_t)gr * DD + (k0 + 8) + ahalf * 4);
            wv = *reinterpret_cast<const float4*>(W + (size_t)(k0 + 8 + wrow) * DD + wcol);
        }

#pragma unroll
        for (int kk = 0; kk < 8; kk++) {
            float4 fa0 = *reinterpret_cast<const float4*>(&As[kk][ty * 8 + 0]);
            float4 fa1 = *reinterpret_cast<const float4*>(&As[kk][ty * 8 + 4]);
            ulonglong2 pb0 = *reinterpret_cast<const ulonglong2*>(&Ws[kk][tx * 8 + 0]);
            ulonglong2 pb1 = *reinterpret_cast<const ulonglong2*>(&Ws[kk][tx * 8 + 4]);
            float af[8] = {fa0.x, fa0.y, fa0.z, fa0.w, fa1.x, fa1.y, fa1.z, fa1.w};
            ull b2[4] = {pb0.x, pb0.y, pb1.x, pb1.y};
            ull a2[8];
#pragma unroll
            for (int i = 0; i < 8; i++) PACK2(a2[i], __float_as_uint(af[i]));
#pragma unroll
            for (int i = 0; i < 8; i++) {
                FMA2(acc2[i][0], a2[i], b2[0]);
                FMA2(acc2[i][1], a2[i], b2[1]);
                FMA2(acc2[i][2], a2[i], b2[2]);
                FMA2(acc2[i][3], a2[i], b2[3]);
            }
        }
        __syncthreads();
    }

#pragma unroll
    for (int i = 0; i < 8; i++) {
        int orow = r0 + ty * 8 + i;
        if (orow < NN) {
            *reinterpret_cast<ulonglong2*>(C + (size_t)orow * DD + tx * 8 + 0) =
                make_ulonglong2(acc2[i][0], acc2[i][1]);
            *reinterpret_cast<ulonglong2*>(C + (size_t)orow * DD + tx * 8 + 4) =
                make_ulonglong2(acc2[i][2], acc2[i][3]);
        }
    }
}

// ---- aggregation: warp/node CSR gather + fused BN-stats block partials ----
__global__ __launch_bounds__(256) void k_agg(
    const float* __restrict__ xw, float* __restrict__ outp,
    float* __restrict__ psum, float* __restrict__ psq, int base)
{
    __shared__ float s1[128], s2[128];
    int t = threadIdx.x;
    if (t < 128) { s1[t] = 0.f; s2[t] = 0.f; }
    __syncthreads();

    int w = base + blockIdx.x * 8 + (t >> 5);
    int lane = t & 31;
    float di = g_dinv[w];

    float4 acc = __ldg(reinterpret_cast<const float4*>(xw + (size_t)w * DD) + lane);
    float cself = di * di;
    acc.x *= cself; acc.y *= cself; acc.z *= cself; acc.w *= cself;

    int beg = g_rowstart[w], end = g_rowstart[w + 1];
    int i = beg;
    for (; i + 3 < end; i += 4) {
        int2 e0 = __ldg(&g_edge[i + 0]);
        int2 e1 = __ldg(&g_edge[i + 1]);
        int2 e2 = __ldg(&g_edge[i + 2]);
        int2 e3 = __ldg(&g_edge[i + 3]);
        float4 v0 = __ldg(reinterpret_cast<const float4*>(xw + (size_t)e0.x * DD) + lane);
        float4 v1 = __ldg(reinterpret_cast<const float4*>(xw + (size_t)e1.x * DD) + lane);
        float4 v2 = __ldg(reinterpret_cast<const float4*>(xw + (size_t)e2.x * DD) + lane);
        float4 v3 = __ldg(reinterpret_cast<const float4*>(xw + (size_t)e3.x * DD) + lane);
        float c0 = di * __int_as_float(e0.y);
        float c1 = di * __int_as_float(e1.y);
        float c2 = di * __int_as_float(e2.y);
        float c3 = di * __int_as_float(e3.y);
        acc.x = fmaf(c0, v0.x, acc.x); acc.y = fmaf(c0, v0.y, acc.y);
        acc.z = fmaf(c0, v0.z, acc.z); acc.w = fmaf(c0, v0.w, acc.w);
        acc.x = fmaf(c1, v1.x, acc.x); acc.y = fmaf(c1, v1.y, acc.y);
        acc.z = fmaf(c1, v1.z, acc.z); acc.w = fmaf(c1, v1.w, acc.w);
        acc.x = fmaf(c2, v2.x, acc.x); acc.y = fmaf(c2, v2.y, acc.y);
        acc.z = fmaf(c2, v2.z, acc.z); acc.w = fmaf(c2, v2.w, acc.w);
        acc.x = fmaf(c3, v3.x, acc.x); acc.y = fmaf(c3, v3.y, acc.y);
        acc.z = fmaf(c3, v3.z, acc.z); acc.w = fmaf(c3, v3.w, acc.w);
    }
    for (; i < end; i++) {
        int2 e0 = __ldg(&g_edge[i]);
        float c0 = di * __int_as_float(e0.y);
        float4 v0 = __ldg(reinterpret_cast<const float4*>(xw + (size_t)e0.x * DD) + lane);
        acc.x = fmaf(c0, v0.x, acc.x); acc.y = fmaf(c0, v0.y, acc.y);
        acc.z = fmaf(c0, v0.z, acc.z); acc.w = fmaf(c0, v0.w, acc.w);
    }
    reinterpret_cast<float4*>(outp + (size_t)w * DD)[lane] = acc;

    // fused BN stats: block partial sums (8 nodes per block)
    atomicAdd(&s1[lane * 4 + 0], acc.x);
    atomicAdd(&s1[lane * 4 + 1], acc.y);
    atomicAdd(&s1[lane * 4 + 2], acc.z);
    atomicAdd(&s1[lane * 4 + 3], acc.w);
    atomicAdd(&s2[lane * 4 + 0], acc.x * acc.x);
    atomicAdd(&s2[lane * 4 + 1], acc.y * acc.y);
    atomicAdd(&s2[lane * 4 + 2], acc.z * acc.z);
    atomicAdd(&s2[lane * 4 + 3], acc.w * acc.w);
    __syncthreads();
    if (t < 128) {
        psum[(size_t)blockIdx.x * DD + t] = s1[t];
        psq [(size_t)blockIdx.x * DD + t] = s2[t];
    }
}

// ---------------- BN stats finalize: block per feature ----------------
__global__ __launch_bounds__(256) void k_stats2(
    const float* __restrict__ gw, const float* __restrict__ be)
{
    __shared__ double r1[256], r2[256];
    int d = blockIdx.x;
    double s = 0.0, q = 0.0;
    for (int b = threadIdx.x; b < NBLK; b += 256) {
        s += (double)g_psum[(size_t)b * DD + d];
        q += (double)g_psq [(size_t)b * DD + d];
    }
    r1[threadIdx.x] = s; r2[threadIdx.x] = q;
    __syncthreads();
    for (int off = 128; off > 0; off >>= 1) {
        if (threadIdx.x < off) {
            r1[threadIdx.x] += r1[threadIdx.x + off];
            r2[threadIdx.x] += r2[threadIdx.x + off];
        }
        __syncthreads();
    }
    if (threadIdx.x == 0) {
        double mu = r1[0] / (double)NN;
        double var = r2[0] / (double)NN - mu * mu;
        float inv = (float)(1.0 / sqrt(var + 1e-5));
        float scl = gw[d] * inv;
        g_scale[d] = scl;
        g_shift[d] = be[d] - (float)mu * scl;
    }
}

// ---------------- final BN apply ----------------
__global__ void k_apply(float* __restrict__ h) {
    int idx = blockIdx.x * blockDim.x + threadIdx.x;   // float4 index
    if (idx < NN * DD / 4) {
        float4 v = reinterpret_cast<float4*>(h)[idx];
        int d = (idx & 31) * 4;
        v.x = v.x * g_scale[d + 0] + g_shift[d + 0];
        v.y = v.y * g_scale[d + 1] + g_shift[d + 1];
        v.z = v.z * g_scale[d + 2] + g_shift[d + 2];
        v.w = v.w * g_scale[d + 3] + g_shift[d + 3];
        reinterpret_cast<float4*>(h)[idx] = v;
    }
}

// ---------------- host launcher ----------------
extern "C" void kernel_launch(void* const* d_in, const int* in_sizes, int n_in,
                              void* d_out, int out_size) {
    const float* x   = (const float*)d_in[0];
    const void*  ei  = d_in[1];
    const float* w0  = (const float*)d_in[2];
    const float* g0  = (const float*)d_in[4];
    const float* be0 = (const float*)d_in[5];
    const float* w1  = (const float*)d_in[6];
    const float* g1  = (const float*)d_in[8];
    const float* be1 = (const float*)d_in[9];
    const float* w2  = (const float*)d_in[10];
    const float* g2  = (const float*)d_in[12];
    const float* be2 = (const float*)d_in[13];
    float* out = (float*)d_out;

    float *xw, *h, *ps, *pq, *scl, *shf;
    cudaGetSymbolAddress((void**)&xw,  g_xw);
    cudaGetSymbolAddress((void**)&h,   g_h);
    cudaGetSymbolAddress((void**)&ps,  g_psum);
    cudaGetSymbolAddress((void**)&pq,  g_psq);
    cudaGetSymbolAddress((void**)&scl, g_scale);
    cudaGetSymbolAddress((void**)&shf, g_shift);

    const int TB = 256;
    int gbG = (NN + 127) / 128;            // 469 GEMM tiles
    int gbA = (NN / 2) / 8;                // 3750 blocks per agg half
    int gbP = (NN * DD / 4 + TB - 1) / TB;
    const int HALF = NN / 2;
    float* psB = ps + (size_t)(HALF / 8) * DD;
    float* pqB = pq + (size_t)(HALF / 8) * DD;

    // layer 0  (launch #4 = agg half B -> ncu capture slot)
    k_build<<<BB, TB>>>(ei);                                   // 1
    k_gemm<<<gbG, TB>>>(x, w0, xw, nullptr, nullptr, 0);       // 2
    k_agg<<<gbA, TB>>>(xw, h, ps, pq, 0);                      // 3
    k_agg<<<gbA, TB>>>(xw, h, psB, pqB, HALF);                 // 4  <- profiled
    k_stats2<<<DD, TB>>>(g0, be0);                             // 5

    // layer 1 (BN0 + LeakyReLU fused into GEMM A-load)
    k_gemm<<<gbG, TB>>>(h, w1, xw, scl, shf, 1);
    k_agg<<<gbA, TB>>>(xw, h, ps, pq, 0);
    k_agg<<<gbA, TB>>>(xw, h, psB, pqB, HALF);
    k_stats2<<<DD, TB>>>(g1, be1);

    // layer 2 (BN1 + LeakyReLU fused), final BN standalone
    k_gemm<<<gbG, TB>>>(h, w2, xw, scl, shf, 1);
    k_agg<<<gbA, TB>>>(xw, out, ps, pq, 0);
    k_agg<<<gbA, TB>>>(xw, out, psB, pqB, HALF);
    k_stats2<<<DD, TB>>>(g2, be2);
    k_apply<<<gbP, TB>>>(out);
}

// round 8
// speedup vs baseline: 1.8244x; 1.1587x over previous
#include <cuda_runtime.h>
#include <cuda_bf16.h>
#include <mma.h>
#include <cstdint>

using namespace nvcuda;

#define NN 60000
#define EE 600000
#define DD 128
#define SLOPE 0.01f
#define BB 256            // build kernel blocks (co-resident)
#define NBLK 7500         // agg stats partial blocks (60000/8)

typedef unsigned long long ull;

// ---------------- device scratch (static, no allocation) ----------------
__device__ int   g_is64;
__device__ int   g_cnt[NN];
__device__ int   g_part[BB];
__device__ int   g_rowstart[NN + 1];
__device__ int   g_next[NN];
__device__ int2  g_edge[EE];
__device__ float g_dinv[NN];
__device__ float g_xw[(size_t)NN * DD];
__device__ float g_h[(size_t)NN * DD];
__device__ float g_psum[(size_t)NBLK * DD];
__device__ float g_psq[(size_t)NBLK * DD];
__device__ float g_scale[DD];
__device__ float g_shift[DD];
__device__ unsigned g_barcnt;
__device__ unsigned g_epoch;
// W as bf16 hi/lo, row-major [k][n]: [layer][hi/lo][128*128]
__device__ __align__(16) __nv_bfloat16 g_wb[3][2][16384];

// ---------------- global spin barrier (BB blocks resident) -----------------
__device__ __forceinline__ void gsync() {
    __syncthreads();
    if (threadIdx.x == 0) {
        __threadfence();
        unsigned e = atomicAdd(&g_epoch, 0u);
        if (atomicAdd(&g_barcnt, 1u) == BB - 1u) {
            g_barcnt = 0u;
            __threadfence();
            atomicAdd(&g_epoch, 1u);
        } else {
            while (((volatile unsigned*)&g_epoch)[0] == e) { __nanosleep(64); }
        }
        __threadfence();
    }
    __syncthreads();
}

__device__ __forceinline__ int edge_at(const void* p, int idx, int is64) {
    return is64 ? ((const int*)p)[2 * idx] : ((const int*)p)[idx];
}

// ---------------- fused CSR build ----------------
__global__ __launch_bounds__(256) void k_build(const void* ei) {
    int t = threadIdx.x, b = blockIdx.x;
    int gid = b * 256 + t;
    const int GSTR = BB * 256;

    if (gid == 0) {
        const long long* q = (const long long*)ei;
        int ok = 1;
        for (int j = 0; j < 256; j++) {
            long long v = q[j];
            if (v < 0 || v >= NN) { ok = 0; break; }
        }
        g_is64 = ok;
    }
    for (int i = gid; i < NN; i += GSTR) g_cnt[i] = 0;
    gsync();
    int is64 = g_is64;

    for (int e = gid; e < EE; e += GSTR) {
        int d = edge_at(ei, EE + e, is64);
        atomicAdd(&g_cnt[d], 1);
    }
    gsync();

    __shared__ int s[256];
    __shared__ int sp[256];
    int i = gid;
    int x = (i < NN) ? g_cnt[i] : 0;
    if (i < NN) g_dinv[i] = rsqrtf((float)(x + 1));
    s[t] = x;
    __syncthreads();
    for (int off = 1; off < 256; off <<= 1) {
        int v = (t >= off) ? s[t - off] : 0;
        __syncthreads();
        s[t] += v;
        __syncthreads();
    }
    int incl = s[t];
    if (t == 255) g_part[b] = incl;
    gsync();

    sp[t] = g_part[t];
    __syncthreads();
    for (int off = 1; off < 256; off <<= 1) {
        int v = (t >= off) ? sp[t - off] : 0;
        __syncthreads();
        sp[t] += v;
        __syncthreads();
    }
    int pre = (b > 0) ? sp[b - 1] : 0;
    if (i < NN) {
        int rs = pre + incl - x;
        g_rowstart[i] = rs;
        g_next[i] = rs;
    }
    if (gid == 0) g_rowstart[NN] = EE;
    gsync();

    for (int e = gid; e < EE; e += GSTR) {
        int sdx = edge_at(ei, e, is64);
        int dd  = edge_at(ei, EE + e, is64);
        int pos = atomicAdd(&g_next[dd], 1);
        g_edge[pos] = make_int2(sdx, __float_as_int(g_dinv[sdx]));
    }
}

// ---------------- W split to bf16 hi/lo (once per call) ----------------
__global__ void k_wconv(const float* __restrict__ w0, const float* __restrict__ w1,
                        const float* __restrict__ w2) {
    const float* W = (blockIdx.x == 0) ? w0 : ((blockIdx.x == 1) ? w1 : w2);
    __nv_bfloat16* d1 = g_wb[blockIdx.x][0];
    __nv_bfloat16* d2 = g_wb[blockIdx.x][1];
    for (int idx = threadIdx.x; idx < 16384; idx += 256) {
        float v = W[idx];
        __nv_bfloat16 h1 = __float2bfloat16(v);
        float r = v - __bfloat162float(h1);
        d1[idx] = h1;
        d2[idx] = __float2bfloat16(r);
    }
}

// ---------------- WMMA GEMM: C = f(A) @ W, split-bf16 (3 products) ---------
// smem layout (bf16, stride 136): A1 A2 B1 B2, each 128x136
#define LDS_STRIDE 136
#define TILE_B (128 * LDS_STRIDE * 2)            // 34816 bytes
#define SM_A1 0
#define SM_A2 (SM_A1 + TILE_B)
#define SM_B1 (SM_A2 + TILE_B)
#define SM_B2 (SM_B1 + TILE_B)
#define SMEMSZ (SM_B2 + TILE_B)                  // 139264 bytes

__global__ __launch_bounds__(256, 1) void k_gemm_w(
    const float* __restrict__ A, int layer, float* __restrict__ C,
    int tile0, int use_bn, int act)
{
    extern __shared__ unsigned char sm[];
    __nv_bfloat16* A1s = (__nv_bfloat16*)(sm + SM_A1);
    __nv_bfloat16* A2s = (__nv_bfloat16*)(sm + SM_A2);
    __nv_bfloat16* B1s = (__nv_bfloat16*)(sm + SM_B1);
    __nv_bfloat16* B2s = (__nv_bfloat16*)(sm + SM_B2);

    int t = threadIdx.x, wid = t >> 5;
    int r0 = (tile0 + blockIdx.x) * 128;

    // stage W hi/lo (vector copy, row-major, restride to 136)
    {
        const uint4* s1 = (const uint4*)g_wb[layer][0];
        const uint4* s2 = (const uint4*)g_wb[layer][1];
        for (int i = t; i < 2048; i += 256) {            // 2048 x 8 bf16
            int row = (i * 8) >> 7, col = (i * 8) & 127;
            *(uint4*)&B1s[row * LDS_STRIDE + col] = s1[i];
            *(uint4*)&B2s[row * LDS_STRIDE + col] = s2[i];
        }
    }
    // stage A split-bf16 with fused BN/act
    for (int i = t; i < 4096; i += 256) {                // 4096 x float4
        int row = (i * 4) >> 7, col = (i * 4) & 127;
        int gr = r0 + row;
        float4 v = make_float4(0.f, 0.f, 0.f, 0.f);
        if (gr < NN) v = *(const float4*)(A + (size_t)gr * DD + col);
        if (use_bn) {
            v.x = v.x * g_scale[col + 0] + g_shift[col + 0];
            v.y = v.y * g_scale[col + 1] + g_shift[col + 1];
            v.z = v.z * g_scale[col + 2] + g_shift[col + 2];
            v.w = v.w * g_scale[col + 3] + g_shift[col + 3];
            if (act) {
                v.x = v.x >= 0.f ? v.x : SLOPE * v.x;
                v.y = v.y >= 0.f ? v.y : SLOPE * v.y;
                v.z = v.z >= 0.f ? v.z : SLOPE * v.z;
                v.w = v.w >= 0.f ? v.w : SLOPE * v.w;
            }
        }
        __nv_bfloat162 h1a = make_bfloat162(__float2bfloat16(v.x), __float2bfloat16(v.y));
        __nv_bfloat162 h1b = make_bfloat162(__float2bfloat16(v.z), __float2bfloat16(v.w));
        float rx = v.x - __bfloat162float(h1a.x);
        float ry = v.y - __bfloat162float(h1a.y);
        float rz = v.z - __bfloat162float(h1b.x);
        float rw = v.w - __bfloat162float(h1b.y);
        __nv_bfloat162 h2a = make_bfloat162(__float2bfloat16(rx), __float2bfloat16(ry));
        __nv_bfloat162 h2b = make_bfloat162(__float2bfloat16(rz), __float2bfloat16(rw));
        __nv_bfloat162* p1 = (__nv_bfloat162*)&A1s[row * LDS_STRIDE + col];
        __nv_bfloat162* p2 = (__nv_bfloat162*)&A2s[row * LDS_STRIDE + col];
        p1[0] = h1a; p1[1] = h1b;
        p2[0] = h2a; p2[1] = h2b;
    }
    __syncthreads();

    // each warp: 16x128 output strip
    wmma::fragment<wmma::accumulator, 16, 16, 16, float> fc[8];
#pragma unroll
    for (int nt = 0; nt < 8; nt++) wmma::fill_fragment(fc[nt], 0.0f);

    for (int ks = 0; ks < 8; ks++) {
        wmma::fragment<wmma::matrix_a, 16, 16, 16, __nv_bfloat16, wmma::row_major> fa1, fa2;
        wmma::load_matrix_sync(fa1, &A1s[(wid * 16) * LDS_STRIDE + ks * 16], LDS_STRIDE);
        wmma::load_matrix_sync(fa2, &A2s[(wid * 16) * LDS_STRIDE + ks * 16], LDS_STRIDE);
#pragma unroll
        for (int nt = 0; nt < 8; nt++) {
            wmma::fragment<wmma::matrix_b, 16, 16, 16, __nv_bfloat16, wmma::row_major> fb1, fb2;
            wmma::load_matrix_sync(fb1, &B1s[(ks * 16) * LDS_STRIDE + nt * 16], LDS_STRIDE);
            wmma::load_matrix_sync(fb2, &B2s[(ks * 16) * LDS_STRIDE + nt * 16], LDS_STRIDE);
            wmma::mma_sync(fc[nt], fa1, fb1, fc[nt]);
            wmma::mma_sync(fc[nt], fa2, fb1, fc[nt]);
            wmma::mma_sync(fc[nt], fa1, fb2, fc[nt]);
        }
    }
    __syncthreads();   // done reading A/B smem (boundary path reuses it)

    int rbase = r0 + wid * 16;
    if (rbase + 16 <= NN) {
#pragma unroll
        for (int nt = 0; nt < 8; nt++)
            wmma::store_matrix_sync(C + (size_t)rbase * DD + nt * 16, fc[nt], DD,
                                    wmma::mem_row_major);
    } else {
        // boundary strip: stage through smem, guarded copy
        float* stage = (float*)sm + wid * 16 * DD;       // 16x128 f32 per warp
#pragma unroll
        for (int nt = 0; nt < 8; nt++)
            wmma::store_matrix_sync(stage + nt * 16, fc[nt], DD, wmma::mem_row_major);
        __syncwarp();
        int lane = t & 31;
        for (int i = lane; i < 16 * 32; i += 32) {       // 16 rows x 32 float4
            int row = i >> 5, c4 = (i & 31) * 4;
            if (rbase + row < NN)
                *(float4*)(C + (size_t)(rbase + row) * DD + c4) =
                    *(float4*)(stage + row * DD + c4);
        }
    }
}

// ---- aggregation: warp/node CSR gather + store-based BN-stats partials ----
__global__ __launch_bounds__(256) void k_agg(
    const float* __restrict__ xw, float* __restrict__ outp,
    float* __restrict__ psum, float* __restrict__ psq)
{
    __shared__ float s1[8][128], s2[8][128];
    int t = threadIdx.x;
    int wid = t >> 5, lane = t & 31;
    int w = blockIdx.x * 8 + wid;
    float di = g_dinv[w];

    float4 acc = __ldg(reinterpret_cast<const float4*>(xw + (size_t)w * DD) + lane);
    float cself = di * di;
    acc.x *= cself; acc.y *= cself; acc.z *= cself; acc.w *= cself;

    int beg = g_rowstart[w], end = g_rowstart[w + 1];
    int i = beg;
    for (; i + 3 < end; i += 4) {
        int2 e0 = __ldg(&g_edge[i + 0]);
        int2 e1 = __ldg(&g_edge[i + 1]);
        int2 e2 = __ldg(&g_edge[i + 2]);
        int2 e3 = __ldg(&g_edge[i + 3]);
        float4 v0 = __ldg(reinterpret_cast<const float4*>(xw + (size_t)e0.x * DD) + lane);
        float4 v1 = __ldg(reinterpret_cast<const float4*>(xw + (size_t)e1.x * DD) + lane);
        float4 v2 = __ldg(reinterpret_cast<const float4*>(xw + (size_t)e2.x * DD) + lane);
        float4 v3 = __ldg(reinterpret_cast<const float4*>(xw + (size_t)e3.x * DD) + lane);
        float c0 = di * __int_as_float(e0.y);
        float c1 = di * __int_as_float(e1.y);
        float c2 = di * __int_as_float(e2.y);
        float c3 = di * __int_as_float(e3.y);
        acc.x = fmaf(c0, v0.x, acc.x); acc.y = fmaf(c0, v0.y, acc.y);
        acc.z = fmaf(c0, v0.z, acc.z); acc.w = fmaf(c0, v0.w, acc.w);
        acc.x = fmaf(c1, v1.x, acc.x); acc.y = fmaf(c1, v1.y, acc.y);
        acc.z = fmaf(c1, v1.z, acc.z); acc.w = fmaf(c1, v1.w, acc.w);
        acc.x = fmaf(c2, v2.x, acc.x); acc.y = fmaf(c2, v2.y, acc.y);
        acc.z = fmaf(c2, v2.z, acc.z); acc.w = fmaf(c2, v2.w, acc.w);
        acc.x = fmaf(c3, v3.x, acc.x); acc.y = fmaf(c3, v3.y, acc.y);
        acc.z = fmaf(c3, v3.z, acc.z); acc.w = fmaf(c3, v3.w, acc.w);
    }
    for (; i < end; i++) {
        int2 e0 = __ldg(&g_edge[i]);
        float c0 = di * __int_as_float(e0.y);
        float4 v0 = __ldg(reinterpret_cast<const float4*>(xw + (size_t)e0.x * DD) + lane);
        acc.x = fmaf(c0, v0.x, acc.x); acc.y = fmaf(c0, v0.y, acc.y);
        acc.z = fmaf(c0, v0.z, acc.z); acc.w = fmaf(c0, v0.w, acc.w);
    }
    reinterpret_cast<float4*>(outp + (size_t)w * DD)[lane] = acc;

    // stats partials: plain stores + tree (no atomics)
    reinterpret_cast<float4*>(&s1[wid][0])[lane] = acc;
    reinterpret_cast<float4*>(&s2[wid][0])[lane] =
        make_float4(acc.x * acc.x, acc.y * acc.y, acc.z * acc.z, acc.w * acc.w);
    __syncthreads();
    if (t < 128) {
        float a = 0.f, b = 0.f;
#pragma unroll
        for (int ww = 0; ww < 8; ww++) { a += s1[ww][t]; b += s2[ww][t]; }
        psum[(size_t)blockIdx.x * DD + t] = a;
        psq [(size_t)blockIdx.x * DD + t] = b;
    }
}

// ---------------- BN stats finalize: block per feature ----------------
__global__ __launch_bounds__(256) void k_stats2(
    const float* __restrict__ gw, const float* __restrict__ be)
{
    __shared__ double r1[256], r2[256];
    int d = blockIdx.x;
    double s = 0.0, q = 0.0;
    for (int b = threadIdx.x; b < NBLK; b += 256) {
        s += (double)g_psum[(size_t)b * DD + d];
        q += (double)g_psq [(size_t)b * DD + d];
    }
    r1[threadIdx.x] = s; r2[threadIdx.x] = q;
    __syncthreads();
    for (int off = 128; off > 0; off >>= 1) {
        if (threadIdx.x < off) {
            r1[threadIdx.x] += r1[threadIdx.x + off];
            r2[threadIdx.x] += r2[threadIdx.x + off];
        }
        __syncthreads();
    }
    if (threadIdx.x == 0) {
        double mu = r1[0] / (double)NN;
        double var = r2[0] / (double)NN - mu * mu;
        float inv = (float)(1.0 / sqrt(var + 1e-5));
        float scl = gw[d] * inv;
        g_scale[d] = scl;
        g_shift[d] = be[d] - (float)mu * scl;
    }
}

// ---------------- final BN apply ----------------
__global__ void k_apply(float* __restrict__ h) {
    int idx = blockIdx.x * blockDim.x + threadIdx.x;
    if (idx < NN * DD / 4) {
        float4 v = reinterpret_cast<float4*>(h)[idx];
        int d = (idx & 31) * 4;
        v.x = v.x * g_scale[d + 0] + g_shift[d + 0];
        v.y = v.y * g_scale[d + 1] + g_shift[d + 1];
        v.z = v.z * g_scale[d + 2] + g_shift[d + 2];
        v.w = v.w * g_scale[d + 3] + g_shift[d + 3];
        reinterpret_cast<float4*>(h)[idx] = v;
    }
}

// ---------------- host launcher ----------------
extern "C" void kernel_launch(void* const* d_in, const int* in_sizes, int n_in,
                              void* d_out, int out_size) {
    const float* x   = (const float*)d_in[0];
    const void*  ei  = d_in[1];
    const float* w0  = (const float*)d_in[2];
    const float* g0  = (const float*)d_in[4];
    const float* be0 = (const float*)d_in[5];
    const float* w1  = (const float*)d_in[6];
    const float* g1  = (const float*)d_in[8];
    const float* be1 = (const float*)d_in[9];
    const float* w2  = (const float*)d_in[10];
    const float* g2  = (const float*)d_in[12];
    const float* be2 = (const float*)d_in[13];
    float* out = (float*)d_out;

    float *xw, *h, *ps, *pq;
    cudaGetSymbolAddress((void**)&xw, g_xw);
    cudaGetSymbolAddress((void**)&h,  g_h);
    cudaGetSymbolAddress((void**)&ps, g_psum);
    cudaGetSymbolAddress((void**)&pq, g_psq);

    static int smem_set = 0;
    if (!smem_set) {
        cudaFuncSetAttribute(k_gemm_w, cudaFuncAttributeMaxDynamicSharedMemorySize, SMEMSZ);
        smem_set = 1;
    }

    const int TB = 256;
    const int TILES = (NN + 127) / 128;   // 469
    const int TSPLIT = 235;
    int gbP = (NN * DD / 4 + TB - 1) / TB;

    // layer 0 (WMMA GEMM occupies launches #3 and #4 -> ncu capture slot)
    k_build<<<BB, TB>>>(ei);                                           // 1
    k_wconv<<<3, TB>>>(w0, w1, w2);                                    // 2
    k_gemm_w<<<TSPLIT, TB, SMEMSZ>>>(x, 0, xw, 0, 0, 0);               // 3
    k_gemm_w<<<TILES - TSPLIT, TB, SMEMSZ>>>(x, 0, xw, TSPLIT, 0, 0);  // 4
    k_agg<<<NBLK, TB>>>(xw, h, ps, pq);                                // 5
    k_stats2<<<DD, TB>>>(g0, be0);                                     // 6

    // layer 1 (BN0 + LeakyReLU fused into A staging)
    k_gemm_w<<<TILES, TB, SMEMSZ>>>(h, 1, xw, 0, 1, 1);
    k_agg<<<NBLK, TB>>>(xw, h, ps, pq);
    k_stats2<<<DD, TB>>>(g1, be1);

    // layer 2 (BN1 + LeakyReLU fused), final BN standalone
    k_gemm_w<<<TILES, TB, SMEMSZ>>>(h, 2, xw, 0, 1, 1);
    k_agg<<<NBLK, TB>>>(xw, out, ps, pq);
    k_stats2<<<DD, TB>>>(g2, be2);
    k_apply<<<gbP, TB>>>(out);
}